// round 10
// baseline (speedup 1.0000x reference)
#include <cuda_runtime.h>
#include <cuda_fp16.h>

// feature_map [512,512,64] f32, boxes [512,4] f32 (cx,cy,w,h), out [512,32,32,64] f32
#define IN_H    512
#define IN_W    512
#define NC4     16          // channels as 4-channel groups
#define NBOX    512
#define OUTW    32
#define OYT     4           // oy rows per CTA tile
#define NTILES  (OUTW / OYT)
#define MAXTAPS 36          // ks < 16  ->  taps <= 2*16+2 = 34
#define MAXROWS 88          // union of 4 oy windows: 3*inv + 2ks + 2 <= 82

typedef unsigned long long ull;

// fp16 staged copy of the feature map (32 MB device scratch; legal per rules).
// +NC4 pad: the paired-tap loop may read one pixel past the logical end at
// (row 511, rightmost window) with zero weight; pad is zero-init .bss.
__device__ uint2 g_fm16[IN_H * IN_W * NC4 + NC4];

// ---- pre-pass: f32 -> fp16 conversion, fully coalesced ----
__global__ __launch_bounds__(1024)
void convert_kernel(const float* __restrict__ fm)
{
    int i = blockIdx.x * 1024 + threadIdx.x;   // one c4 group per thread
    const float4 v = ((const float4*)fm)[i];
    __half2 a = __floats2half2_rn(v.x, v.y);
    __half2 b = __floats2half2_rn(v.z, v.w);
    uint2 o;
    o.x = *reinterpret_cast<unsigned*>(&a);
    o.y = *reinterpret_cast<unsigned*>(&b);
    g_fm16[i] = o;
}

// half2 (packed in u32) -> f32x2 (packed in u64), lane order preserved
__device__ __forceinline__ ull h2_to_f32x2(unsigned h2)
{
    ull r;
    asm("{\n\t"
        ".reg .f16 a, b;\n\t"
        ".reg .f32 lo, hi;\n\t"
        "mov.b32 {a, b}, %1;\n\t"
        "cvt.f32.f16 lo, a;\n\t"
        "cvt.f32.f16 hi, b;\n\t"
        "mov.b64 %0, {lo, hi};\n\t"
        "}" : "=l"(r) : "r"(h2));
    return r;
}

// packed dual-FMA: acc.lane += v.lane * w.lane  (IEEE f32 per lane)
#define FMA2(acc, v, w) \
    asm("fma.rn.f32x2 %0, %1, %2, %0;" : "+l"(acc) : "l"(v), "l"(w))

// One CTA per (box, oy-tile of 4). 512 threads = 32 ox x 16 c4 lanes.
// Inner loop kept register-lean (target: no spills at 42 regs / 3 CTA/SM):
// single r01/r23 chains, LDS.128-paired weight loads.
// Weight math replicates jax.image.scale_and_translate(method="linear",
// antialias=True) exactly (formulas verified since R4).
__global__ __launch_bounds__(512, 3)
void roi_align_kernel(const float* __restrict__ boxes,
                      float* __restrict__ out)
{
    __shared__ float2 s_wx2[OUTW * MAXTAPS];    // x weights, duplicated {w,w}
    __shared__ int    s_xb[OUTW];               // x window base per ox
    __shared__ float  s_sy[OYT];                // y sample pos per tile oy
    __shared__ float  s_invn[OYT];              // y norm (0 if invalid)
    __shared__ int    s_yb[OYT];                // y window base per tile oy
    __shared__ float2 s_wyt2[MAXROWS * OYT];    // y weights, duplicated {w,w}

    const int tile = blockIdx.x;   // 0..7
    const int box  = blockIdx.y;   // 0..511
    const int tid  = threadIdx.x;

    // ---- box parameters (all threads) ----
    const float4 b = ((const float4*)boxes)[box];
    float x0 = b.x - b.z * 0.5f;           // pre-clamp w/h (reference order)
    float y0 = b.y - b.w * 0.5f;
    float bw = fmaxf(b.z, 1e-6f);
    float bh = fmaxf(b.w, 1e-6f);

    float scale_x = 32.0f / (bw * 512.0f);
    float inv_x   = 1.0f / scale_x;
    float ks_x    = fmaxf(inv_x, 1.0f);
    float toff_x  = ((-x0 * 32.0f) / bw) * inv_x;
    int   ntx     = min((int)(2.0f * ks_x) + 2, MAXTAPS);

    float scale_y = 32.0f / (bh * 512.0f);
    float inv_y   = 1.0f / scale_y;
    float ks_y    = fmaxf(inv_y, 1.0f);
    float toff_y  = ((-y0 * 32.0f) / bh) * inv_y;
    int   nty     = min((int)(2.0f * ks_y) + 2, MAXTAPS);
    float rks_y   = 1.0f / ks_y;

    // ---- phase 1: per-ox x weights (threads 0..31), per-oy y params (32..35)
    if (tid < OUTW) {
        const int ox = tid;
        float s    = ((float)ox + 0.5f) * inv_x - toff_x - 0.5f;
        int   base = min(max((int)ceilf(s - ks_x), 0), IN_W - ntx);
        float rks  = 1.0f / ks_x;
        float norm = 0.0f;
        for (int j = 0; j < ntx; j++)
            norm += fmaxf(0.0f, 1.0f - fabsf(s - (float)(base + j)) * rks);
        bool valid = (s >= -0.5f) && (s <= (float)IN_W - 0.5f)
                     && (fabsf(norm) > 1.1920929e-4f);   // 1000 * eps_f32
        float invn = valid ? (1.0f / norm) : 0.0f;
        for (int j = 0; j < ntx; j++) {
            float w = fmaxf(0.0f, 1.0f - fabsf(s - (float)(base + j)) * rks) * invn;
            s_wx2[ox * MAXTAPS + j] = make_float2(w, w);
        }
        // pad one tap past the end: the paired (j, j+1) loop reads ntx
        // rounded up to even; the extra tap must weigh zero
        if (ntx < MAXTAPS) s_wx2[ox * MAXTAPS + ntx] = make_float2(0.f, 0.f);
        s_xb[ox] = base;
    } else if (tid < OUTW + OYT) {
        const int k  = tid - OUTW;
        const int oy = tile * OYT + k;
        float sy = ((float)oy + 0.5f) * inv_y - toff_y - 0.5f;
        int   yb = min(max((int)ceilf(sy - ks_y), 0), IN_H - nty);
        float norm = 0.0f;
        for (int j = 0; j < nty; j++)
            norm += fmaxf(0.0f, 1.0f - fabsf(sy - (float)(yb + j)) * rks_y);
        bool valid = (sy >= -0.5f) && (sy <= (float)IN_H - 0.5f)
                     && (fabsf(norm) > 1.1920929e-4f);
        s_sy[k]   = sy;
        s_invn[k] = valid ? (1.0f / norm) : 0.0f;
        s_yb[k]   = yb;
    }
    __syncthreads();

    // ---- phase 2: fill duplicated wy table over the row union ----
    const int rmin   = s_yb[0];                       // sy monotone in k
    const int rcount = s_yb[OYT - 1] + nty - rmin;    // <= 82
    for (int idx = tid; idx < rcount * OYT; idx += 512) {
        int r = idx >> 2, k = idx & (OYT - 1);
        float w = fmaxf(0.0f, 1.0f - fabsf(s_sy[k] - (float)(rmin + r)) * rks_y)
                  * s_invn[k];
        s_wyt2[idx] = make_float2(w, w);
    }
    __syncthreads();

    // active rows form one interval (y-windows of the 4 oy overlap)
    const int rlo = max(rmin, (int)ceilf(s_sy[0] - ks_y));
    const int rhi = min(rmin + rcount, (int)floorf(s_sy[OYT - 1] + ks_y) + 1);

    // ---- main loop: thread = (ox, c4), 4 oy f32x2-pair accumulators ----
    const int ox = tid >> 4;
    const int c4 = tid & 15;
    // 16B-aligned pair pointer over this ox's weight row (MAXTAPS even)
    const ulonglong2* __restrict__ wxp =
        (const ulonglong2*)&s_wx2[ox * MAXTAPS];
    const int njp = (ntx + 1) >> 1;   // tap pairs (zero-padded tap covers odd)

    ull a01_0 = 0, a23_0 = 0, a01_1 = 0, a23_1 = 0;
    ull a01_2 = 0, a23_2 = 0, a01_3 = 0, a23_3 = 0;

    const uint2* __restrict__ rowp =
        g_fm16 + ((size_t)rlo * IN_W + s_xb[ox]) * NC4 + c4;
    const ulonglong2* __restrict__ wyp =
        (const ulonglong2*)&s_wyt2[(rlo - rmin) * OYT];

    for (int r = rlo; r < rhi; r++) {
        // x convolution for this row: paired taps, two FMA2 chains
        ull r01 = 0, r23 = 0;
        const uint2* __restrict__ p = rowp;
        for (int jp = 0; jp < njp; jp++) {
            ulonglong2 w01 = wxp[jp];         // LDS.128: 2 duplicated weights
            uint2 v0 = p[0];
            uint2 v1 = p[NC4];                // may touch zero-weight pad tap
            FMA2(r01, h2_to_f32x2(v0.x), w01.x);
            FMA2(r23, h2_to_f32x2(v0.y), w01.x);
            FMA2(r01, h2_to_f32x2(v1.x), w01.y);
            FMA2(r23, h2_to_f32x2(v1.y), w01.y);
            p += 2 * NC4;
        }

        // scatter into 4 oy accumulators; wy pairs via 2 x LDS.128
        ulonglong2 wy01 = wyp[0];
        ulonglong2 wy23 = wyp[1];
        FMA2(a01_0, r01, wy01.x);  FMA2(a23_0, r23, wy01.x);
        FMA2(a01_1, r01, wy01.y);  FMA2(a23_1, r23, wy01.y);
        FMA2(a01_2, r01, wy23.x);  FMA2(a23_2, r23, wy23.x);
        FMA2(a01_3, r01, wy23.y);  FMA2(a23_3, r23, wy23.y);

        rowp += IN_W * NC4;
        wyp  += 2;              // OYT pairs per row = 2 ulonglong2
    }

    // ---- write out[box][tile*4+k][ox][c] ----
    {
        float2* __restrict__ out2 = (float2*)out;
        size_t base =
            ((((size_t)box * OUTW + tile * OYT) * OUTW + ox) * NC4 + c4) * 2;
        const size_t oystep = (size_t)OUTW * NC4 * 2;
        out2[base + 0]              = *reinterpret_cast<float2*>(&a01_0);
        out2[base + 1]              = *reinterpret_cast<float2*>(&a23_0);
        out2[base + oystep + 0]     = *reinterpret_cast<float2*>(&a01_1);
        out2[base + oystep + 1]     = *reinterpret_cast<float2*>(&a23_1);
        out2[base + 2 * oystep + 0] = *reinterpret_cast<float2*>(&a01_2);
        out2[base + 2 * oystep + 1] = *reinterpret_cast<float2*>(&a23_2);
        out2[base + 3 * oystep + 0] = *reinterpret_cast<float2*>(&a01_3);
        out2[base + 3 * oystep + 1] = *reinterpret_cast<float2*>(&a23_3);
    }
}

extern "C" void kernel_launch(void* const* d_in, const int* in_sizes, int n_in,
                              void* d_out, int out_size)
{
    const float* fm    = (const float*)d_in[0];   // [512, 512, 64] f32
    const float* boxes = (const float*)d_in[1];   // [512, 4] f32
    float* out = (float*)d_out;                   // [512, 32, 32, 64] f32

    // pre-pass: stage feature map as fp16 (16.7M elems / 4 per thread)
    convert_kernel<<<(IN_H * IN_W * NC4) / 1024, 1024>>>(fm);

    dim3 grid(NTILES, NBOX);   // (oy-tile, box) -> 4096 CTAs
    roi_align_kernel<<<grid, 512>>>(boxes, out);
}

// round 11
// speedup vs baseline: 1.3130x; 1.3130x over previous
#include <cuda_runtime.h>
#include <cuda_fp16.h>

// feature_map [512,512,64] f32, boxes [512,4] f32 (cx,cy,w,h), out [512,32,32,64] f32
#define IN_H    512
#define IN_W    512
#define NC4     16          // channels as 4-channel groups
#define NBOX    512
#define OUTW    32
#define OYT     8           // oy rows per CTA tile (R7 champion shape)
#define NTILES  (OUTW / OYT)
#define MAXTAPS 40          // ks < 16 -> taps <= 34; +4 zero pads for quad loop
#define MAXROWS 152         // union of 8 oy windows: 7*inv + 2ks + 2 < 146

typedef unsigned long long ull;

// fp16 staged copy of the feature map (32 MB device scratch; legal per rules).
// +64 px pad: quad-tap loop may read up to 3 px past the logical end at
// (row 511, rightmost window) with zero weight; pad is zero-init .bss.
__device__ uint2 g_fm16[(IN_H * IN_W + 64) * NC4];

// ---- pre-pass: f32 -> fp16 conversion, fully coalesced ----
__global__ __launch_bounds__(1024)
void convert_kernel(const float* __restrict__ fm)
{
    int i = blockIdx.x * 1024 + threadIdx.x;   // one c4 group per thread
    const float4 v = ((const float4*)fm)[i];
    __half2 a = __floats2half2_rn(v.x, v.y);
    __half2 b = __floats2half2_rn(v.z, v.w);
    uint2 o;
    o.x = *reinterpret_cast<unsigned*>(&a);
    o.y = *reinterpret_cast<unsigned*>(&b);
    g_fm16[i] = o;
}

// half2 (packed in u32) -> f32x2 (packed in u64), lane order preserved
__device__ __forceinline__ ull h2f(unsigned h2)
{
    ull r;
    asm("{\n\t"
        ".reg .f16 a, b;\n\t"
        ".reg .f32 lo, hi;\n\t"
        "mov.b32 {a, b}, %1;\n\t"
        "cvt.f32.f16 lo, a;\n\t"
        "cvt.f32.f16 hi, b;\n\t"
        "mov.b64 %0, {lo, hi};\n\t"
        "}" : "=l"(r) : "r"(h2));
    return r;
}

// packed dual-FMA: acc.lane += v.lane * w.lane  (IEEE f32 per lane)
#define FMA2(acc, v, w) \
    asm("fma.rn.f32x2 %0, %1, %2, %0;" : "+l"(acc) : "l"(v), "l"(w))
#define ADD2(dst, a, b) \
    asm("add.rn.f32x2 %0, %1, %2;" : "=l"(dst) : "l"(a), "l"(b))

// One CTA per (box, oy-tile of 8). 512 threads = 32 ox x 16 c4 lanes.
// 2 CTAs/SM at 64 regs: the register budget is spent on load batching (MLP).
// Inner loop: tap quads — 4 LDG.64 issued before any FMA, dual even/odd
// FMA2 chains, LDS.128-paired weights.
// Weight math replicates jax.image.scale_and_translate(method="linear",
// antialias=True) exactly (formulas verified since R4).
__global__ __launch_bounds__(512, 2)
void roi_align_kernel(const float* __restrict__ boxes,
                      float* __restrict__ out)
{
    __shared__ float2 s_wx2[OUTW * MAXTAPS];    // x weights, duplicated {w,w}
    __shared__ int    s_xb[OUTW];               // x window base per ox
    __shared__ float  s_sy[OYT];                // y sample pos per tile oy
    __shared__ float  s_invn[OYT];              // y norm (0 if invalid)
    __shared__ int    s_yb[OYT];                // y window base per tile oy
    __shared__ float2 s_wyt2[MAXROWS * OYT];    // y weights, duplicated {w,w}

    const int tile = blockIdx.x;   // 0..3
    const int box  = blockIdx.y;   // 0..511
    const int tid  = threadIdx.x;

    // ---- box parameters (all threads) ----
    const float4 b = ((const float4*)boxes)[box];
    float x0 = b.x - b.z * 0.5f;           // pre-clamp w/h (reference order)
    float y0 = b.y - b.w * 0.5f;
    float bw = fmaxf(b.z, 1e-6f);
    float bh = fmaxf(b.w, 1e-6f);

    float scale_x = 32.0f / (bw * 512.0f);
    float inv_x   = 1.0f / scale_x;
    float ks_x    = fmaxf(inv_x, 1.0f);
    float toff_x  = ((-x0 * 32.0f) / bw) * inv_x;
    int   ntx     = min((int)(2.0f * ks_x) + 2, 34);

    float scale_y = 32.0f / (bh * 512.0f);
    float inv_y   = 1.0f / scale_y;
    float ks_y    = fmaxf(inv_y, 1.0f);
    float toff_y  = ((-y0 * 32.0f) / bh) * inv_y;
    int   nty     = min((int)(2.0f * ks_y) + 2, 34);
    float rks_y   = 1.0f / ks_y;

    // ---- phase 1: per-ox x weights (threads 0..31), per-oy y params (32..39)
    if (tid < OUTW) {
        const int ox = tid;
        float s    = ((float)ox + 0.5f) * inv_x - toff_x - 0.5f;
        int   base = min(max((int)ceilf(s - ks_x), 0), IN_W - ntx);
        float rks  = 1.0f / ks_x;
        float norm = 0.0f;
        for (int j = 0; j < ntx; j++)
            norm += fmaxf(0.0f, 1.0f - fabsf(s - (float)(base + j)) * rks);
        bool valid = (s >= -0.5f) && (s <= (float)IN_W - 0.5f)
                     && (fabsf(norm) > 1.1920929e-4f);   // 1000 * eps_f32
        float invn = valid ? (1.0f / norm) : 0.0f;
        for (int j = 0; j < ntx; j++) {
            float w = fmaxf(0.0f, 1.0f - fabsf(s - (float)(base + j)) * rks) * invn;
            s_wx2[ox * MAXTAPS + j] = make_float2(w, w);
        }
        // zero-pad to the quad boundary (up to 4 taps; ntx+4 <= 38 < 40)
        #pragma unroll
        for (int j = 0; j < 4; j++)
            s_wx2[ox * MAXTAPS + ntx + j] = make_float2(0.f, 0.f);
        s_xb[ox] = base;
    } else if (tid < OUTW + OYT) {
        const int k  = tid - OUTW;
        const int oy = tile * OYT + k;
        float sy = ((float)oy + 0.5f) * inv_y - toff_y - 0.5f;
        int   yb = min(max((int)ceilf(sy - ks_y), 0), IN_H - nty);
        float norm = 0.0f;
        for (int j = 0; j < nty; j++)
            norm += fmaxf(0.0f, 1.0f - fabsf(sy - (float)(yb + j)) * rks_y);
        bool valid = (sy >= -0.5f) && (sy <= (float)IN_H - 0.5f)
                     && (fabsf(norm) > 1.1920929e-4f);
        s_sy[k]   = sy;
        s_invn[k] = valid ? (1.0f / norm) : 0.0f;
        s_yb[k]   = yb;
    }
    __syncthreads();

    // ---- phase 2: fill duplicated wy table over the row union ----
    const int rmin   = s_yb[0];                       // sy monotone in k
    const int rcount = s_yb[OYT - 1] + nty - rmin;    // <= 146
    for (int idx = tid; idx < rcount * OYT; idx += 512) {
        int r = idx >> 3, k = idx & (OYT - 1);
        float w = fmaxf(0.0f, 1.0f - fabsf(s_sy[k] - (float)(rmin + r)) * rks_y)
                  * s_invn[k];
        s_wyt2[idx] = make_float2(w, w);
    }
    __syncthreads();

    // active rows form one interval (y-windows of the 8 oy overlap)
    const int rlo = max(rmin, (int)ceilf(s_sy[0] - ks_y));
    const int rhi = min(rmin + rcount, (int)floorf(s_sy[OYT - 1] + ks_y) + 1);

    // ---- main loop: thread = (ox, c4), 8 oy f32x2-pair accumulators ----
    const int ox = tid >> 4;
    const int c4 = tid & 15;
    const ulonglong2* __restrict__ wxq =
        (const ulonglong2*)&s_wx2[ox * MAXTAPS];   // 16B-aligned weight pairs
    const int nq = (ntx + 3) >> 2;                 // tap quads (zero-padded)

    ull a01_0 = 0, a23_0 = 0, a01_1 = 0, a23_1 = 0;
    ull a01_2 = 0, a23_2 = 0, a01_3 = 0, a23_3 = 0;
    ull a01_4 = 0, a23_4 = 0, a01_5 = 0, a23_5 = 0;
    ull a01_6 = 0, a23_6 = 0, a01_7 = 0, a23_7 = 0;

    const uint2* __restrict__ rowp =
        g_fm16 + ((size_t)rlo * IN_W + s_xb[ox]) * NC4 + c4;
    const ulonglong2* __restrict__ wyp =
        (const ulonglong2*)&s_wyt2[(rlo - rmin) * OYT];

    for (int r = rlo; r < rhi; r++) {
        // x convolution: quads of taps, all 4 loads issued before the FMAs,
        // dual even/odd accumulator chains
        ull r01a = 0, r23a = 0, r01b = 0, r23b = 0;
        const uint2* __restrict__ p = rowp;
        for (int q = 0; q < nq; q++) {
            uint2 v0 = p[0];
            uint2 v1 = p[NC4];
            uint2 v2 = p[2 * NC4];
            uint2 v3 = p[3 * NC4];
            ulonglong2 wA = wxq[2 * q];        // taps j, j+1
            ulonglong2 wB = wxq[2 * q + 1];    // taps j+2, j+3
            FMA2(r01a, h2f(v0.x), wA.x);  FMA2(r23a, h2f(v0.y), wA.x);
            FMA2(r01b, h2f(v1.x), wA.y);  FMA2(r23b, h2f(v1.y), wA.y);
            FMA2(r01a, h2f(v2.x), wB.x);  FMA2(r23a, h2f(v2.y), wB.x);
            FMA2(r01b, h2f(v3.x), wB.y);  FMA2(r23b, h2f(v3.y), wB.y);
            p += 4 * NC4;
        }
        ull r01, r23;
        ADD2(r01, r01a, r01b);
        ADD2(r23, r23a, r23b);

        // scatter into 8 oy accumulators; wy pairs via 4 x LDS.128
        ulonglong2 wy01 = wyp[0];
        ulonglong2 wy23 = wyp[1];
        ulonglong2 wy45 = wyp[2];
        ulonglong2 wy67 = wyp[3];
        FMA2(a01_0, r01, wy01.x);  FMA2(a23_0, r23, wy01.x);
        FMA2(a01_1, r01, wy01.y);  FMA2(a23_1, r23, wy01.y);
        FMA2(a01_2, r01, wy23.x);  FMA2(a23_2, r23, wy23.x);
        FMA2(a01_3, r01, wy23.y);  FMA2(a23_3, r23, wy23.y);
        FMA2(a01_4, r01, wy45.x);  FMA2(a23_4, r23, wy45.x);
        FMA2(a01_5, r01, wy45.y);  FMA2(a23_5, r23, wy45.y);
        FMA2(a01_6, r01, wy67.x);  FMA2(a23_6, r23, wy67.x);
        FMA2(a01_7, r01, wy67.y);  FMA2(a23_7, r23, wy67.y);

        rowp += IN_W * NC4;
        wyp  += 4;              // OYT pairs per row = 4 ulonglong2
    }

    // ---- write out[box][tile*8+k][ox][c] ----
    {
        float2* __restrict__ out2 = (float2*)out;
        size_t base =
            ((((size_t)box * OUTW + tile * OYT) * OUTW + ox) * NC4 + c4) * 2;
        const size_t st = (size_t)OUTW * NC4 * 2;
        out2[base + 0]      = *reinterpret_cast<float2*>(&a01_0);
        out2[base + 1]      = *reinterpret_cast<float2*>(&a23_0);
        out2[base + st + 0] = *reinterpret_cast<float2*>(&a01_1);
        out2[base + st + 1] = *reinterpret_cast<float2*>(&a23_1);
        out2[base + 2*st + 0] = *reinterpret_cast<float2*>(&a01_2);
        out2[base + 2*st + 1] = *reinterpret_cast<float2*>(&a23_2);
        out2[base + 3*st + 0] = *reinterpret_cast<float2*>(&a01_3);
        out2[base + 3*st + 1] = *reinterpret_cast<float2*>(&a23_3);
        out2[base + 4*st + 0] = *reinterpret_cast<float2*>(&a01_4);
        out2[base + 4*st + 1] = *reinterpret_cast<float2*>(&a23_4);
        out2[base + 5*st + 0] = *reinterpret_cast<float2*>(&a01_5);
        out2[base + 5*st + 1] = *reinterpret_cast<float2*>(&a23_5);
        out2[base + 6*st + 0] = *reinterpret_cast<float2*>(&a01_6);
        out2[base + 6*st + 1] = *reinterpret_cast<float2*>(&a23_6);
        out2[base + 7*st + 0] = *reinterpret_cast<float2*>(&a01_7);
        out2[base + 7*st + 1] = *reinterpret_cast<float2*>(&a23_7);
    }
}

extern "C" void kernel_launch(void* const* d_in, const int* in_sizes, int n_in,
                              void* d_out, int out_size)
{
    const float* fm    = (const float*)d_in[0];   // [512, 512, 64] f32
    const float* boxes = (const float*)d_in[1];   // [512, 4] f32
    float* out = (float*)d_out;                   // [512, 32, 32, 64] f32

    // pre-pass: stage feature map as fp16 (16.7M elems / 4 per thread)
    convert_kernel<<<(IN_H * IN_W * NC4) / 1024, 1024>>>(fm);

    dim3 grid(NTILES, NBOX);   // (oy-tile, box) -> 2048 CTAs
    roi_align_kernel<<<grid, 512>>>(boxes, out);
}

// round 12
// speedup vs baseline: 1.3533x; 1.0307x over previous
#include <cuda_runtime.h>
#include <cuda_fp16.h>

// feature_map [512,512,64] f32, boxes [512,4] f32 (cx,cy,w,h), out [512,32,32,64] f32
#define IN_H    512
#define IN_W    512
#define NC8     8           // channels as 8-channel groups (uint4 of 4 half2)
#define NBOX    512
#define OUTW    32
#define OYT     4           // oy rows per CTA tile
#define NTILES  (OUTW / OYT)
#define MAXTAPS 36          // ks < 16 -> taps <= 34; +pair pad
#define MAXROWS 88          // union of 4 oy windows: 3*inv + 2ks + 2 <= 82

typedef unsigned long long ull;

// fp16 staged copy of the feature map (32 MB device scratch; legal per rules).
// +64 px pad: pair-tap loop may read 1 px past the logical end at
// (row 511, rightmost window) with zero weight; pad is zero-init .bss.
// Layout: uint4 per (pixel, c8-group): 8 halves = 16 bytes.
__device__ uint4 g_fm16[(IN_H * IN_W + 64) * NC8];

// ---- pre-pass: f32 -> fp16 conversion, fully coalesced ----
__global__ __launch_bounds__(1024)
void convert_kernel(const float* __restrict__ fm)
{
    int i = blockIdx.x * 1024 + threadIdx.x;   // one c8 group per thread
    const float4 v0 = ((const float4*)fm)[2 * i];
    const float4 v1 = ((const float4*)fm)[2 * i + 1];
    __half2 a = __floats2half2_rn(v0.x, v0.y);
    __half2 b = __floats2half2_rn(v0.z, v0.w);
    __half2 c = __floats2half2_rn(v1.x, v1.y);
    __half2 d = __floats2half2_rn(v1.z, v1.w);
    uint4 o;
    o.x = *reinterpret_cast<unsigned*>(&a);
    o.y = *reinterpret_cast<unsigned*>(&b);
    o.z = *reinterpret_cast<unsigned*>(&c);
    o.w = *reinterpret_cast<unsigned*>(&d);
    g_fm16[i] = o;
}

// half2 (packed in u32) -> f32x2 (packed in u64), lane order preserved
__device__ __forceinline__ ull h2f(unsigned h2)
{
    ull r;
    asm("{\n\t"
        ".reg .f16 a, b;\n\t"
        ".reg .f32 lo, hi;\n\t"
        "mov.b32 {a, b}, %1;\n\t"
        "cvt.f32.f16 lo, a;\n\t"
        "cvt.f32.f16 hi, b;\n\t"
        "mov.b64 %0, {lo, hi};\n\t"
        "}" : "=l"(r) : "r"(h2));
    return r;
}

// packed dual-FMA: acc.lane += v.lane * w.lane  (IEEE f32 per lane)
#define FMA2(acc, v, w) \
    asm("fma.rn.f32x2 %0, %1, %2, %0;" : "+l"(acc) : "l"(v), "l"(w))

// One CTA per (box, oy-tile of 4). 256 threads = 32 ox x 8 c8 lanes.
// Each thread covers 8 channels per tap via one LDG.128 — cuts per-channel
// instruction count ~30% vs the c4 layout at the same 32-warp/SM operating
// point (64 regs, 4 CTA/SM).
// Weight math replicates jax.image.scale_and_translate(method="linear",
// antialias=True) exactly (formulas verified since R4).
__global__ __launch_bounds__(256, 4)
void roi_align_kernel(const float* __restrict__ boxes,
                      float* __restrict__ out)
{
    __shared__ float2 s_wx2[OUTW * MAXTAPS];    // x weights, duplicated {w,w}
    __shared__ int    s_xb[OUTW];               // x window base per ox
    __shared__ float  s_sy[OYT];                // y sample pos per tile oy
    __shared__ float  s_invn[OYT];              // y norm (0 if invalid)
    __shared__ int    s_yb[OYT];                // y window base per tile oy
    __shared__ float2 s_wyt2[MAXROWS * OYT];    // y weights, duplicated {w,w}

    const int tile = blockIdx.x;   // 0..7
    const int box  = blockIdx.y;   // 0..511
    const int tid  = threadIdx.x;

    // ---- box parameters (all threads) ----
    const float4 b = ((const float4*)boxes)[box];
    float x0 = b.x - b.z * 0.5f;           // pre-clamp w/h (reference order)
    float y0 = b.y - b.w * 0.5f;
    float bw = fmaxf(b.z, 1e-6f);
    float bh = fmaxf(b.w, 1e-6f);

    float scale_x = 32.0f / (bw * 512.0f);
    float inv_x   = 1.0f / scale_x;
    float ks_x    = fmaxf(inv_x, 1.0f);
    float toff_x  = ((-x0 * 32.0f) / bw) * inv_x;
    int   ntx     = min((int)(2.0f * ks_x) + 2, 34);

    float scale_y = 32.0f / (bh * 512.0f);
    float inv_y   = 1.0f / scale_y;
    float ks_y    = fmaxf(inv_y, 1.0f);
    float toff_y  = ((-y0 * 32.0f) / bh) * inv_y;
    int   nty     = min((int)(2.0f * ks_y) + 2, 34);
    float rks_y   = 1.0f / ks_y;

    // ---- phase 1: per-ox x weights (threads 0..31), per-oy y params (32..35)
    if (tid < OUTW) {
        const int ox = tid;
        float s    = ((float)ox + 0.5f) * inv_x - toff_x - 0.5f;
        int   base = min(max((int)ceilf(s - ks_x), 0), IN_W - ntx);
        float rks  = 1.0f / ks_x;
        float norm = 0.0f;
        for (int j = 0; j < ntx; j++)
            norm += fmaxf(0.0f, 1.0f - fabsf(s - (float)(base + j)) * rks);
        bool valid = (s >= -0.5f) && (s <= (float)IN_W - 0.5f)
                     && (fabsf(norm) > 1.1920929e-4f);   // 1000 * eps_f32
        float invn = valid ? (1.0f / norm) : 0.0f;
        for (int j = 0; j < ntx; j++) {
            float w = fmaxf(0.0f, 1.0f - fabsf(s - (float)(base + j)) * rks) * invn;
            s_wx2[ox * MAXTAPS + j] = make_float2(w, w);
        }
        // zero-pad one tap (pair loop rounds ntx up to even; ntx+1 <= 35 < 36)
        s_wx2[ox * MAXTAPS + ntx] = make_float2(0.f, 0.f);
        s_xb[ox] = base;
    } else if (tid < OUTW + OYT) {
        const int k  = tid - OUTW;
        const int oy = tile * OYT + k;
        float sy = ((float)oy + 0.5f) * inv_y - toff_y - 0.5f;
        int   yb = min(max((int)ceilf(sy - ks_y), 0), IN_H - nty);
        float norm = 0.0f;
        for (int j = 0; j < nty; j++)
            norm += fmaxf(0.0f, 1.0f - fabsf(sy - (float)(yb + j)) * rks_y);
        bool valid = (sy >= -0.5f) && (sy <= (float)IN_H - 0.5f)
                     && (fabsf(norm) > 1.1920929e-4f);
        s_sy[k]   = sy;
        s_invn[k] = valid ? (1.0f / norm) : 0.0f;
        s_yb[k]   = yb;
    }
    __syncthreads();

    // ---- phase 2: fill duplicated wy table over the row union ----
    const int rmin   = s_yb[0];                       // sy monotone in k
    const int rcount = s_yb[OYT - 1] + nty - rmin;    // <= 82
    for (int idx = tid; idx < rcount * OYT; idx += 256) {
        int r = idx >> 2, k = idx & (OYT - 1);
        float w = fmaxf(0.0f, 1.0f - fabsf(s_sy[k] - (float)(rmin + r)) * rks_y)
                  * s_invn[k];
        s_wyt2[idx] = make_float2(w, w);
    }
    __syncthreads();

    // active rows form one interval (y-windows of the 4 oy overlap)
    const int rlo = max(rmin, (int)ceilf(s_sy[0] - ks_y));
    const int rhi = min(rmin + rcount, (int)floorf(s_sy[OYT - 1] + ks_y) + 1);

    // ---- main loop: thread = (ox, c8); 4 oy x 8 ch accumulators ----
    const int ox = tid >> 3;        // 0..31
    const int c8 = tid & 7;         // 0..7
    const ulonglong2* __restrict__ wxp =
        (const ulonglong2*)&s_wx2[ox * MAXTAPS];   // 16B-aligned weight pairs
    const int np = (ntx + 1) >> 1;                 // tap pairs (zero-padded)

    // accumulators: a[k][p] = oy k, channel pair p (ch 2p, 2p+1)
    ull a0_0 = 0, a0_1 = 0, a0_2 = 0, a0_3 = 0;
    ull a1_0 = 0, a1_1 = 0, a1_2 = 0, a1_3 = 0;
    ull a2_0 = 0, a2_1 = 0, a2_2 = 0, a2_3 = 0;
    ull a3_0 = 0, a3_1 = 0, a3_2 = 0, a3_3 = 0;

    const uint4* __restrict__ rowp =
        g_fm16 + ((size_t)rlo * IN_W + s_xb[ox]) * NC8 + c8;
    const ulonglong2* __restrict__ wyp =
        (const ulonglong2*)&s_wyt2[(rlo - rmin) * OYT];

    for (int r = rlo; r < rhi; r++) {
        // x convolution: pairs of taps, both LDG.128 issued before the FMAs
        ull r01 = 0, r23 = 0, r45 = 0, r67 = 0;
        const uint4* __restrict__ p = rowp;
        for (int jp = 0; jp < np; jp++) {
            uint4 v0 = p[0];
            uint4 v1 = p[NC8];                 // may touch zero-weight pad tap
            ulonglong2 w01 = wxp[jp];          // LDS.128: 2 duplicated weights
            FMA2(r01, h2f(v0.x), w01.x);
            FMA2(r23, h2f(v0.y), w01.x);
            FMA2(r45, h2f(v0.z), w01.x);
            FMA2(r67, h2f(v0.w), w01.x);
            FMA2(r01, h2f(v1.x), w01.y);
            FMA2(r23, h2f(v1.y), w01.y);
            FMA2(r45, h2f(v1.z), w01.y);
            FMA2(r67, h2f(v1.w), w01.y);
            p += 2 * NC8;
        }

        // scatter into 4 oy accumulators; wy pairs via 2 x LDS.128
        ulonglong2 wy01 = wyp[0];
        ulonglong2 wy23 = wyp[1];
        FMA2(a0_0, r01, wy01.x);  FMA2(a0_1, r23, wy01.x);
        FMA2(a0_2, r45, wy01.x);  FMA2(a0_3, r67, wy01.x);
        FMA2(a1_0, r01, wy01.y);  FMA2(a1_1, r23, wy01.y);
        FMA2(a1_2, r45, wy01.y);  FMA2(a1_3, r67, wy01.y);
        FMA2(a2_0, r01, wy23.x);  FMA2(a2_1, r23, wy23.x);
        FMA2(a2_2, r45, wy23.x);  FMA2(a2_3, r67, wy23.x);
        FMA2(a3_0, r01, wy23.y);  FMA2(a3_1, r23, wy23.y);
        FMA2(a3_2, r45, wy23.y);  FMA2(a3_3, r67, wy23.y);

        rowp += IN_W * NC8;
        wyp  += 2;              // OYT pairs per row = 2 ulonglong2
    }

    // ---- write out[box][tile*4+k][ox][c8*8 .. +7] ----
    {
        float2* __restrict__ out2 = (float2*)out;
        size_t base =
            ((((size_t)box * OUTW + tile * OYT) * OUTW + ox) * NC8 + c8) * 4;
        const size_t st = (size_t)OUTW * NC8 * 4;   // one oy step in float2
        out2[base + 0] = *reinterpret_cast<float2*>(&a0_0);
        out2[base + 1] = *reinterpret_cast<float2*>(&a0_1);
        out2[base + 2] = *reinterpret_cast<float2*>(&a0_2);
        out2[base + 3] = *reinterpret_cast<float2*>(&a0_3);
        out2[base + st + 0] = *reinterpret_cast<float2*>(&a1_0);
        out2[base + st + 1] = *reinterpret_cast<float2*>(&a1_1);
        out2[base + st + 2] = *reinterpret_cast<float2*>(&a1_2);
        out2[base + st + 3] = *reinterpret_cast<float2*>(&a1_3);
        out2[base + 2*st + 0] = *reinterpret_cast<float2*>(&a2_0);
        out2[base + 2*st + 1] = *reinterpret_cast<float2*>(&a2_1);
        out2[base + 2*st + 2] = *reinterpret_cast<float2*>(&a2_2);
        out2[base + 2*st + 3] = *reinterpret_cast<float2*>(&a2_3);
        out2[base + 3*st + 0] = *reinterpret_cast<float2*>(&a3_0);
        out2[base + 3*st + 1] = *reinterpret_cast<float2*>(&a3_1);
        out2[base + 3*st + 2] = *reinterpret_cast<float2*>(&a3_2);
        out2[base + 3*st + 3] = *reinterpret_cast<float2*>(&a3_3);
    }
}

extern "C" void kernel_launch(void* const* d_in, const int* in_sizes, int n_in,
                              void* d_out, int out_size)
{
    const float* fm    = (const float*)d_in[0];   // [512, 512, 64] f32
    const float* boxes = (const float*)d_in[1];   // [512, 4] f32
    float* out = (float*)d_out;                   // [512, 32, 32, 64] f32

    // pre-pass: stage feature map as fp16 (2.1M c8-groups, 8 ch per thread)
    convert_kernel<<<(IN_H * IN_W * NC8) / 1024, 1024>>>(fm);

    dim3 grid(NTILES, NBOX);   // (oy-tile, box) -> 4096 CTAs
    roi_align_kernel<<<grid, 256>>>(boxes, out);
}